// round 2
// baseline (speedup 1.0000x reference)
#include <cuda_runtime.h>
#include <math.h>

#define NPG 286        // nodes per graph
#define EPG 4000       // edges per graph
#define NGRAPH 8192
#define THREADS 512
#define FDIM 3

__global__ __launch_bounds__(THREADS)
void gnn_kernel(const float* __restrict__ feat,
                const int*   __restrict__ src,
                const int*   __restrict__ dst,
                const float* __restrict__ W1, const float* __restrict__ b1,
                const float* __restrict__ W2, const float* __restrict__ b2,
                const float* __restrict__ Wfc, const float* __restrict__ bfc,
                float* __restrict__ out)
{
    __shared__ unsigned int   s_edge[EPG];      // low16 = src local, high16 = dst local
    __shared__ unsigned short s_csr[EPG];       // src local, sorted by dst
    __shared__ int   s_scan[THREADS];
    __shared__ int   s_row[NPG + 1];
    __shared__ int   s_cnt[NPG];                // deg_in count, then scatter cursor
    __shared__ int   s_degout[NPG];
    __shared__ float s_nin[NPG];
    __shared__ float s_nout[NPG];
    __shared__ float4 s_bufA[NPG];
    __shared__ float4 s_bufB[NPG];
    __shared__ float s_red[16];

    const int g    = blockIdx.x;
    const int tid  = threadIdx.x;
    const int base = g * NPG;
    const int* __restrict__ srcp = src + (long long)g * EPG;
    const int* __restrict__ dstp = dst + (long long)g * EPG;

    // ---- init counters ----
    for (int i = tid; i < NPG; i += THREADS) { s_cnt[i] = 0; s_degout[i] = 0; }
    __syncthreads();

    // ---- load edges (coalesced, DRAM once), count degrees ----
    for (int e = tid; e < EPG; e += THREADS) {
        int s = srcp[e] - base;
        int d = dstp[e] - base;
        s_edge[e] = (unsigned)s | ((unsigned)d << 16);
        atomicAdd(&s_degout[s], 1);
        atomicAdd(&s_cnt[d], 1);
    }
    __syncthreads();

    // ---- inclusive scan of deg_in -> exclusive row offsets ----
    int deg_in_v = (tid < NPG) ? s_cnt[tid] : 0;
    s_scan[tid] = deg_in_v;
    __syncthreads();
    #pragma unroll
    for (int off = 1; off < THREADS; off <<= 1) {
        int t = s_scan[tid];
        if (tid >= off) t += s_scan[tid - off];
        __syncthreads();
        s_scan[tid] = t;
        __syncthreads();
    }
    if (tid < NPG) {
        int excl = s_scan[tid] - deg_in_v;
        s_row[tid] = excl;
        s_cnt[tid] = excl;  // scatter cursor
        s_nin[tid]  = rsqrtf(fmaxf((float)deg_in_v, 1.0f));
        s_nout[tid] = rsqrtf(fmaxf((float)s_degout[tid], 1.0f));
    }
    if (tid == 0) s_row[NPG] = EPG;
    __syncthreads();

    // ---- scatter: counting sort edges by dst ----
    for (int e = tid; e < EPG; e += THREADS) {
        unsigned sd = s_edge[e];
        int d = (int)(sd >> 16);
        int pos = atomicAdd(&s_cnt[d], 1);
        s_csr[pos] = (unsigned short)(sd & 0xFFFFu);
    }

    // ---- load features, pre-scale by norm_out -> bufA holds y0 ----
    if (tid < NPG) {
        const float* fp = feat + (long long)(base + tid) * FDIM;
        float no = s_nout[tid];
        s_bufA[tid] = make_float4(fp[0] * no, fp[1] * no, fp[2] * no, 0.f);
    }
    __syncthreads();

    // weights into registers (uniform broadcast, L1/L2 hot)
    float w1[9], w2[9], bb1[3], bb2[3];
    #pragma unroll
    for (int i = 0; i < 9; i++) { w1[i] = __ldg(W1 + i); w2[i] = __ldg(W2 + i); }
    #pragma unroll
    for (int i = 0; i < 3; i++) { bb1[i] = __ldg(b1 + i); bb2[i] = __ldg(b2 + i); }

    // ---- layer 1: gather over in-edges (atomic-free) ----
    if (tid < NPG) {
        int d = tid;
        float ax = 0.f, ay = 0.f, az = 0.f;
        int e0 = s_row[d], e1 = s_row[d + 1];
        for (int e = e0; e < e1; e++) {
            float4 y = s_bufA[s_csr[e]];
            ax += y.x; ay += y.y; az += y.z;
        }
        float ni = s_nin[d];
        ax *= ni; ay *= ni; az *= ni;
        float o0 = fmaxf(fmaf(ax, w1[0], fmaf(ay, w1[3], fmaf(az, w1[6], bb1[0]))), 0.f);
        float o1 = fmaxf(fmaf(ax, w1[1], fmaf(ay, w1[4], fmaf(az, w1[7], bb1[1]))), 0.f);
        float o2 = fmaxf(fmaf(ax, w1[2], fmaf(ay, w1[5], fmaf(az, w1[8], bb1[2]))), 0.f);
        float no = s_nout[d];
        s_bufB[d] = make_float4(o0 * no, o1 * no, o2 * no, 0.f);  // y1
    }
    __syncthreads();

    // ---- layer 2: gather, output raw x2 into bufA ----
    if (tid < NPG) {
        int d = tid;
        float ax = 0.f, ay = 0.f, az = 0.f;
        int e0 = s_row[d], e1 = s_row[d + 1];
        for (int e = e0; e < e1; e++) {
            float4 y = s_bufB[s_csr[e]];
            ax += y.x; ay += y.y; az += y.z;
        }
        float ni = s_nin[d];
        ax *= ni; ay *= ni; az *= ni;
        float o0 = fmaxf(fmaf(ax, w2[0], fmaf(ay, w2[3], fmaf(az, w2[6], bb2[0]))), 0.f);
        float o1 = fmaxf(fmaf(ax, w2[1], fmaf(ay, w2[4], fmaf(az, w2[7], bb2[1]))), 0.f);
        float o2 = fmaxf(fmaf(ax, w2[2], fmaf(ay, w2[5], fmaf(az, w2[8], bb2[2]))), 0.f);
        s_bufA[d] = make_float4(o0, o1, o2, 0.f);  // raw x2
    }
    __syncthreads();

    // ---- FC: out[g] = sigmoid( sum_k x2_flat[k] * Wfc[k] + bfc ) ----
    const float* xf = (const float*)s_bufA;  // node i, feat j at index i*4 + j
    float acc = 0.f;
    for (int k = tid; k < NPG * FDIM; k += THREADS) {
        int i = k / 3;
        int j = k - 3 * i;
        acc += xf[i * 4 + j] * __ldg(Wfc + k);
    }
    // block reduce
    #pragma unroll
    for (int o = 16; o > 0; o >>= 1) acc += __shfl_down_sync(0xFFFFFFFFu, acc, o);
    if ((tid & 31) == 0) s_red[tid >> 5] = acc;
    __syncthreads();
    if (tid < 32) {
        float v = (tid < (THREADS / 32)) ? s_red[tid] : 0.f;
        #pragma unroll
        for (int o = 8; o > 0; o >>= 1) v += __shfl_down_sync(0xFFFFFFFFu, v, o);
        if (tid == 0) {
            float z = v + __ldg(bfc);
            out[g] = 1.0f / (1.0f + expf(-z));
        }
    }
}

extern "C" void kernel_launch(void* const* d_in, const int* in_sizes, int n_in,
                              void* d_out, int out_size)
{
    const float* feat = (const float*)d_in[0];
    const int*   src  = (const int*)  d_in[1];
    const int*   dst  = (const int*)  d_in[2];
    const float* W1   = (const float*)d_in[3];
    const float* b1   = (const float*)d_in[4];
    const float* W2   = (const float*)d_in[5];
    const float* b2   = (const float*)d_in[6];
    const float* Wfc  = (const float*)d_in[7];
    const float* bfc  = (const float*)d_in[8];

    int ngraph = out_size > 0 ? out_size : NGRAPH;
    gnn_kernel<<<ngraph, THREADS>>>(feat, src, dst, W1, b1, W2, b2, Wfc, bfc,
                                    (float*)d_out);
}

// round 3
// speedup vs baseline: 1.2056x; 1.2056x over previous
#include <cuda_runtime.h>
#include <math.h>

#define NPG 286        // nodes per graph
#define EPG 4000       // edges per graph
#define NGRAPH 8192
#define THREADS 512
#define FDIM 3

__global__ __launch_bounds__(THREADS)
void gnn_kernel(const float* __restrict__ feat,
                const int*   __restrict__ src,
                const int*   __restrict__ dst,
                const float* __restrict__ W1, const float* __restrict__ b1,
                const float* __restrict__ W2, const float* __restrict__ b2,
                const float* __restrict__ Wfc, const float* __restrict__ bfc,
                float* __restrict__ out)
{
    __shared__ unsigned int s_edge[EPG];   // low16 = src, high16 = dst (load order)
    __shared__ unsigned int s_csr[EPG];    // low16 = src, high16 = dst, sorted by dst
    __shared__ float s_fx[NPG], s_fy[NPG], s_fz[NPG];   // per-node features (pre-scaled)
    __shared__ float s_ax[NPG], s_ay[NPG], s_az[NPG];   // aggregation accumulators
    __shared__ int   s_degin[NPG];
    __shared__ int   s_degout[NPG];
    __shared__ int   s_cur[NPG];           // scatter cursor
    __shared__ float s_nin[NPG];
    __shared__ float s_nout[NPG];
    __shared__ int   s_wsum[16];
    __shared__ float s_red[16];

    const int g    = blockIdx.x;
    const int tid  = threadIdx.x;
    const int lane = tid & 31;
    const int warp = tid >> 5;
    const int base = g * NPG;
    const int* __restrict__ srcp = src + (long long)g * EPG;
    const int* __restrict__ dstp = dst + (long long)g * EPG;

    // ---- init counters ----
    if (tid < NPG) { s_degin[tid] = 0; s_degout[tid] = 0; }
    __syncthreads();

    // ---- load edges (coalesced), count degrees ----
    for (int e = tid; e < EPG; e += THREADS) {
        int s = srcp[e] - base;
        int d = dstp[e] - base;
        s_edge[e] = (unsigned)s | ((unsigned)d << 16);
        atomicAdd(&s_degout[s], 1);
        atomicAdd(&s_degin[d], 1);
    }
    __syncthreads();

    // ---- warp-shfl scan of deg_in -> exclusive offsets (cursors) + norms ----
    int degv = (tid < NPG) ? s_degin[tid] : 0;
    int v = degv;
    #pragma unroll
    for (int o = 1; o < 32; o <<= 1) {
        int n = __shfl_up_sync(0xFFFFFFFFu, v, o);
        if (lane >= o) v += n;
    }
    if (lane == 31) s_wsum[warp] = v;
    __syncthreads();
    if (warp == 0 && lane < 16) {
        int w = s_wsum[lane];
        #pragma unroll
        for (int o = 1; o < 16; o <<= 1) {
            int n = __shfl_up_sync(0xFFFFu, w, o);
            if (lane >= o) w += n;
        }
        s_wsum[lane] = w;
    }
    __syncthreads();
    if (tid < NPG) {
        int incl = v + (warp ? s_wsum[warp - 1] : 0);
        s_cur[tid]  = incl - degv;                     // exclusive offset = cursor
        s_nin[tid]  = rsqrtf(fmaxf((float)degv, 1.0f));
        s_nout[tid] = rsqrtf(fmaxf((float)s_degout[tid], 1.0f));
    }
    __syncthreads();

    // ---- counting-sort scatter: edges sorted by dst ----
    for (int e = tid; e < EPG; e += THREADS) {
        unsigned sd = s_edge[e];
        int d = (int)(sd >> 16);
        int pos = atomicAdd(&s_cur[d], 1);
        s_csr[pos] = sd;
    }

    // ---- load features coalesced, scale by norm_out, SoA; zero accumulators ----
    {
        const float* fbase = feat + (long long)base * FDIM;
        for (int k = tid; k < NPG * FDIM; k += THREADS) {
            int i = k / 3;
            int j = k - 3 * i;
            float val = fbase[k] * s_nout[i];
            if      (j == 0) s_fx[i] = val;
            else if (j == 1) s_fy[i] = val;
            else             s_fz[i] = val;
        }
        if (tid < NPG) { s_ax[tid] = 0.f; s_ay[tid] = 0.f; s_az[tid] = 0.f; }
    }
    __syncthreads();

    // ===================== layer 1: edge-parallel segmented gather =====================
    {
        int e0 = (tid * EPG) / THREADS;
        int e1 = ((tid + 1) * EPG) / THREADS;
        unsigned sd = s_csr[e0];
        int cur = (int)(sd >> 16);
        int s   = (int)(sd & 0xFFFFu);
        float ax = s_fx[s], ay = s_fy[s], az = s_fz[s];
        for (int e = e0 + 1; e < e1; e++) {
            sd = s_csr[e];
            int d = (int)(sd >> 16);
            s = (int)(sd & 0xFFFFu);
            float vx = s_fx[s], vy = s_fy[s], vz = s_fz[s];
            if (d != cur) {
                atomicAdd(&s_ax[cur], ax);
                atomicAdd(&s_ay[cur], ay);
                atomicAdd(&s_az[cur], az);
                cur = d; ax = vx; ay = vy; az = vz;
            } else {
                ax += vx; ay += vy; az += vz;
            }
        }
        atomicAdd(&s_ax[cur], ax);
        atomicAdd(&s_ay[cur], ay);
        atomicAdd(&s_az[cur], az);
    }
    __syncthreads();

    // ---- layer 1 node transform: norm_in, W1, relu, pre-scale next norm_out ----
    if (tid < NPG) {
        float ni = s_nin[tid];
        float ax = s_ax[tid] * ni, ay = s_ay[tid] * ni, az = s_az[tid] * ni;
        float o0 = fmaxf(fmaf(ax, __ldg(W1+0), fmaf(ay, __ldg(W1+3), fmaf(az, __ldg(W1+6), __ldg(b1+0)))), 0.f);
        float o1 = fmaxf(fmaf(ax, __ldg(W1+1), fmaf(ay, __ldg(W1+4), fmaf(az, __ldg(W1+7), __ldg(b1+1)))), 0.f);
        float o2 = fmaxf(fmaf(ax, __ldg(W1+2), fmaf(ay, __ldg(W1+5), fmaf(az, __ldg(W1+8), __ldg(b1+2)))), 0.f);
        float no = s_nout[tid];
        s_fx[tid] = o0 * no; s_fy[tid] = o1 * no; s_fz[tid] = o2 * no;
        s_ax[tid] = 0.f; s_ay[tid] = 0.f; s_az[tid] = 0.f;
    }
    __syncthreads();

    // ===================== layer 2: edge-parallel segmented gather =====================
    {
        int e0 = (tid * EPG) / THREADS;
        int e1 = ((tid + 1) * EPG) / THREADS;
        unsigned sd = s_csr[e0];
        int cur = (int)(sd >> 16);
        int s   = (int)(sd & 0xFFFFu);
        float ax = s_fx[s], ay = s_fy[s], az = s_fz[s];
        for (int e = e0 + 1; e < e1; e++) {
            sd = s_csr[e];
            int d = (int)(sd >> 16);
            s = (int)(sd & 0xFFFFu);
            float vx = s_fx[s], vy = s_fy[s], vz = s_fz[s];
            if (d != cur) {
                atomicAdd(&s_ax[cur], ax);
                atomicAdd(&s_ay[cur], ay);
                atomicAdd(&s_az[cur], az);
                cur = d; ax = vx; ay = vy; az = vz;
            } else {
                ax += vx; ay += vy; az += vz;
            }
        }
        atomicAdd(&s_ax[cur], ax);
        atomicAdd(&s_ay[cur], ay);
        atomicAdd(&s_az[cur], az);
    }
    __syncthreads();

    // ---- layer 2 node transform: raw outputs into accumulators ----
    if (tid < NPG) {
        float ni = s_nin[tid];
        float ax = s_ax[tid] * ni, ay = s_ay[tid] * ni, az = s_az[tid] * ni;
        float o0 = fmaxf(fmaf(ax, __ldg(W2+0), fmaf(ay, __ldg(W2+3), fmaf(az, __ldg(W2+6), __ldg(b2+0)))), 0.f);
        float o1 = fmaxf(fmaf(ax, __ldg(W2+1), fmaf(ay, __ldg(W2+4), fmaf(az, __ldg(W2+7), __ldg(b2+1)))), 0.f);
        float o2 = fmaxf(fmaf(ax, __ldg(W2+2), fmaf(ay, __ldg(W2+5), fmaf(az, __ldg(W2+8), __ldg(b2+2)))), 0.f);
        s_ax[tid] = o0; s_ay[tid] = o1; s_az[tid] = o2;
    }
    __syncthreads();

    // ---- FC: out[g] = sigmoid( sum_k x2_flat[k] * Wfc[k] + bfc ) ----
    float acc = 0.f;
    for (int k = tid; k < NPG * FDIM; k += THREADS) {
        int i = k / 3;
        int j = k - 3 * i;
        float val = (j == 0) ? s_ax[i] : (j == 1) ? s_ay[i] : s_az[i];
        acc += val * __ldg(Wfc + k);
    }
    #pragma unroll
    for (int o = 16; o > 0; o >>= 1) acc += __shfl_down_sync(0xFFFFFFFFu, acc, o);
    if (lane == 0) s_red[warp] = acc;
    __syncthreads();
    if (tid < 32) {
        float vv = (tid < (THREADS / 32)) ? s_red[tid] : 0.f;
        #pragma unroll
        for (int o = 8; o > 0; o >>= 1) vv += __shfl_down_sync(0xFFFFFFFFu, vv, o);
        if (tid == 0) {
            float z = vv + __ldg(bfc);
            out[g] = 1.0f / (1.0f + expf(-z));
        }
    }
}

extern "C" void kernel_launch(void* const* d_in, const int* in_sizes, int n_in,
                              void* d_out, int out_size)
{
    const float* feat = (const float*)d_in[0];
    const int*   src  = (const int*)  d_in[1];
    const int*   dst  = (const int*)  d_in[2];
    const float* W1   = (const float*)d_in[3];
    const float* b1   = (const float*)d_in[4];
    const float* W2   = (const float*)d_in[5];
    const float* b2   = (const float*)d_in[6];
    const float* Wfc  = (const float*)d_in[7];
    const float* bfc  = (const float*)d_in[8];

    int ngraph = out_size > 0 ? out_size : NGRAPH;
    gnn_kernel<<<ngraph, THREADS>>>(feat, src, dst, W1, b1, W2, b2, Wfc, bfc,
                                    (float*)d_out);
}